// round 1
// baseline (speedup 1.0000x reference)
#include <cuda_runtime.h>
#include <cuda_bf16.h>
#include <cstdint>

// ---------------------------------------------------------------------------
// AttentionSampling: B=4, SQ=2048, SK=8192, D=H=512, F=4, fp32.
//   q = relu(query@w_q + b_q)            [4,2048,512]
//   k = relu(key@w_k + b_k)              [4,8192,512]
//   v = value@w_v + b_v                  [4,8192,512]
//   w[b,4s+f] = q[b,s,:]. k[b,4s+f,:]
//   ao[b,s,:] = sum_f w[b,4s+f] * v[b,4s+f,:]
//   out1 = LN(q + ao; ln1)
//   ffn  = relu(out1@ffn_w1 + ffn_b1) @ ffn_w2 + ffn_b2
//   out  = LN(out1 + ffn; ln2)
// ---------------------------------------------------------------------------

#define DD 512
#define NROWS_Q   (4 * 2048)   // 8192
#define NROWS_KV  (4 * 8192)   // 32768
#define EPS 1e-5f

// Scratch: q | out1 | h | ffn | k | v  (fp32)
#define OFF_Q    0
#define OFF_OUT1 (OFF_Q    + (size_t)NROWS_Q  * DD)
#define OFF_H    (OFF_OUT1 + (size_t)NROWS_Q  * DD)
#define OFF_FFN  (OFF_H    + (size_t)NROWS_Q  * DD)
#define OFF_K    (OFF_FFN  + (size_t)NROWS_Q  * DD)
#define OFF_V    (OFF_K    + (size_t)NROWS_KV * DD)
#define SCRATCH_ELEMS (OFF_V + (size_t)NROWS_KV * DD)

__device__ float g_scratch[SCRATCH_ELEMS];

// ---------------------------------------------------------------------------
// SGEMM: C[M,512] = act(A[M,512] @ B[512,512] + bias), fp32.
// 128x128 block tile, BK=16, 256 threads, 8x8 per-thread microtile,
// double-buffered shared memory. M must be a multiple of 128 (it is).
// ---------------------------------------------------------------------------
template <bool RELU>
__global__ void __launch_bounds__(256, 2) sgemm_bias(
    const float* __restrict__ A, const float* __restrict__ B,
    const float* __restrict__ bias, float* __restrict__ C)
{
    __shared__ float As[2][16][132];
    __shared__ float Bs[2][16][132];

    const int bm = blockIdx.y * 128;
    const int bn = blockIdx.x * 128;
    const int tid = threadIdx.x;
    const int tx = tid & 15;         // 0..15  -> 8 output cols
    const int ty = tid >> 4;         // 0..15  -> 8 output rows
    const int arow = tid >> 2;       // 0..63
    const int acol = (tid & 3) << 2; // 0,4,8,12
    const int brow = tid >> 5;       // 0..7
    const int bcol = (tid & 31) << 2;

    const float* Ag = A + (size_t)(bm + arow) * DD + acol;
    const float* Bg = B + (size_t)brow * DD + bn + bcol;

    float4 pa0 = *(const float4*)(Ag);
    float4 pa1 = *(const float4*)(Ag + (size_t)64 * DD);
    float4 pb0 = *(const float4*)(Bg);
    float4 pb1 = *(const float4*)(Bg + (size_t)8 * DD);

    float acc[8][8];
#pragma unroll
    for (int i = 0; i < 8; i++)
#pragma unroll
        for (int j = 0; j < 8; j++) acc[i][j] = 0.f;

    // stage tile 0
    As[0][acol + 0][arow] = pa0.x; As[0][acol + 1][arow] = pa0.y;
    As[0][acol + 2][arow] = pa0.z; As[0][acol + 3][arow] = pa0.w;
    As[0][acol + 0][arow + 64] = pa1.x; As[0][acol + 1][arow + 64] = pa1.y;
    As[0][acol + 2][arow + 64] = pa1.z; As[0][acol + 3][arow + 64] = pa1.w;
    *(float4*)&Bs[0][brow][bcol] = pb0;
    *(float4*)&Bs[0][brow + 8][bcol] = pb1;
    __syncthreads();

    int buf = 0;
#pragma unroll 1
    for (int k0 = 16; k0 <= DD; k0 += 16) {
        if (k0 < DD) {
            pa0 = *(const float4*)(Ag + k0);
            pa1 = *(const float4*)(Ag + (size_t)64 * DD + k0);
            pb0 = *(const float4*)(Bg + (size_t)k0 * DD);
            pb1 = *(const float4*)(Bg + (size_t)(k0 + 8) * DD);
        }
#pragma unroll
        for (int kk = 0; kk < 16; kk++) {
            float a[8], b[8];
#pragma unroll
            for (int i = 0; i < 8; i++) a[i] = As[buf][kk][ty * 8 + i];
#pragma unroll
            for (int j = 0; j < 8; j++) b[j] = Bs[buf][kk][tx * 8 + j];
#pragma unroll
            for (int i = 0; i < 8; i++)
#pragma unroll
                for (int j = 0; j < 8; j++) acc[i][j] += a[i] * b[j];
        }
        if (k0 < DD) {
            int nb = buf ^ 1;
            As[nb][acol + 0][arow] = pa0.x; As[nb][acol + 1][arow] = pa0.y;
            As[nb][acol + 2][arow] = pa0.z; As[nb][acol + 3][arow] = pa0.w;
            As[nb][acol + 0][arow + 64] = pa1.x; As[nb][acol + 1][arow + 64] = pa1.y;
            As[nb][acol + 2][arow + 64] = pa1.z; As[nb][acol + 3][arow + 64] = pa1.w;
            *(float4*)&Bs[nb][brow][bcol] = pb0;
            *(float4*)&Bs[nb][brow + 8][bcol] = pb1;
            __syncthreads();
            buf = nb;
        }
    }

#pragma unroll
    for (int i = 0; i < 8; i++) {
        int row = bm + ty * 8 + i;
#pragma unroll
        for (int j = 0; j < 8; j += 4) {
            int col = bn + tx * 8 + j;
            float4 bv = *(const float4*)(bias + col);
            float4 o;
            o.x = acc[i][j + 0] + bv.x;
            o.y = acc[i][j + 1] + bv.y;
            o.z = acc[i][j + 2] + bv.z;
            o.w = acc[i][j + 3] + bv.w;
            if (RELU) {
                o.x = fmaxf(o.x, 0.f); o.y = fmaxf(o.y, 0.f);
                o.z = fmaxf(o.z, 0.f); o.w = fmaxf(o.w, 0.f);
            }
            *(float4*)(C + (size_t)row * DD + col) = o;
        }
    }
}

// ---------------------------------------------------------------------------
// Reductions
// ---------------------------------------------------------------------------
__device__ __forceinline__ float warp_sum(float x) {
#pragma unroll
    for (int o = 16; o > 0; o >>= 1) x += __shfl_xor_sync(0xffffffffu, x, o);
    return x;
}

// ---------------------------------------------------------------------------
// Fused attention downsampling + residual + LayerNorm1.
// One block (256 threads) per output row (b,s). Each thread owns d=tid, tid+256.
// ---------------------------------------------------------------------------
__global__ void __launch_bounds__(256) attn_ln_kernel(
    const float* __restrict__ q, const float* __restrict__ k,
    const float* __restrict__ v, const float* __restrict__ gamma,
    const float* __restrict__ beta, float* __restrict__ out)
{
    const int row = blockIdx.x;                 // b*2048+s
    const float* qr = q + (size_t)row * DD;
    const float* kr = k + (size_t)row * 4 * DD; // rows 4s..4s+3 of batch b
    const float* vr = v + (size_t)row * 4 * DD;
    const int tid = threadIdx.x;
    const int lane = tid & 31, wid = tid >> 5;

    float q0 = qr[tid], q1 = qr[tid + 256];

    float p[4];
#pragma unroll
    for (int f = 0; f < 4; f++)
        p[f] = q0 * kr[f * DD + tid] + q1 * kr[f * DD + tid + 256];

    __shared__ float red[4][8];
#pragma unroll
    for (int f = 0; f < 4; f++) {
        float s = warp_sum(p[f]);
        if (lane == 0) red[f][wid] = s;
    }
    __syncthreads();
    __shared__ float wsh[4];
    if (tid < 4) {
        float s = 0.f;
#pragma unroll
        for (int i = 0; i < 8; i++) s += red[tid][i];
        wsh[tid] = s;
    }
    __syncthreads();
    const float w0 = wsh[0], w1 = wsh[1], w2 = wsh[2], w3 = wsh[3];

    float r0 = q0 + w0 * vr[tid]           + w1 * vr[DD + tid]
                  + w2 * vr[2 * DD + tid]  + w3 * vr[3 * DD + tid];
    float r1 = q1 + w0 * vr[tid + 256]          + w1 * vr[DD + tid + 256]
                  + w2 * vr[2 * DD + tid + 256] + w3 * vr[3 * DD + tid + 256];

    // LayerNorm over 512
    float s = warp_sum(r0 + r1);
    float ss = warp_sum(r0 * r0 + r1 * r1);
    __shared__ float rs[8], rss[8];
    if (lane == 0) { rs[wid] = s; rss[wid] = ss; }
    __syncthreads();
    __shared__ float mv[2];
    if (tid == 0) {
        float S = 0.f, SS = 0.f;
#pragma unroll
        for (int i = 0; i < 8; i++) { S += rs[i]; SS += rss[i]; }
        float mean = S * (1.f / 512.f);
        float var = SS * (1.f / 512.f) - mean * mean;
        mv[0] = mean; mv[1] = rsqrtf(var + EPS);
    }
    __syncthreads();
    const float mean = mv[0], inv = mv[1];
    float* orow = out + (size_t)row * DD;
    orow[tid]       = (r0 - mean) * inv * gamma[tid]       + beta[tid];
    orow[tid + 256] = (r1 - mean) * inv * gamma[tid + 256] + beta[tid + 256];
}

// ---------------------------------------------------------------------------
// Fused residual + LayerNorm2 -> final output.
// ---------------------------------------------------------------------------
__global__ void __launch_bounds__(256) resid_ln_kernel(
    const float* __restrict__ a, const float* __restrict__ f,
    const float* __restrict__ gamma, const float* __restrict__ beta,
    float* __restrict__ out)
{
    const int row = blockIdx.x;
    const int tid = threadIdx.x;
    const int lane = tid & 31, wid = tid >> 5;
    const size_t off = (size_t)row * DD;

    float r0 = a[off + tid]       + f[off + tid];
    float r1 = a[off + tid + 256] + f[off + tid + 256];

    float s = warp_sum(r0 + r1);
    float ss = warp_sum(r0 * r0 + r1 * r1);
    __shared__ float rs[8], rss[8];
    if (lane == 0) { rs[wid] = s; rss[wid] = ss; }
    __syncthreads();
    __shared__ float mv[2];
    if (tid == 0) {
        float S = 0.f, SS = 0.f;
#pragma unroll
        for (int i = 0; i < 8; i++) { S += rs[i]; SS += rss[i]; }
        float mean = S * (1.f / 512.f);
        float var = SS * (1.f / 512.f) - mean * mean;
        mv[0] = mean; mv[1] = rsqrtf(var + EPS);
    }
    __syncthreads();
    const float mean = mv[0], inv = mv[1];
    out[off + tid]       = (r0 - mean) * inv * gamma[tid]       + beta[tid];
    out[off + tid + 256] = (r1 - mean) * inv * gamma[tid + 256] + beta[tid + 256];
}

// ---------------------------------------------------------------------------
// Launch
// ---------------------------------------------------------------------------
extern "C" void kernel_launch(void* const* d_in, const int* in_sizes, int n_in,
                              void* d_out, int out_size)
{
    const float* query  = (const float*)d_in[0];
    const float* key    = (const float*)d_in[1];
    const float* value  = (const float*)d_in[2];
    const float* w_q    = (const float*)d_in[3];
    const float* b_q    = (const float*)d_in[4];
    const float* w_k    = (const float*)d_in[5];
    const float* b_k    = (const float*)d_in[6];
    const float* w_v    = (const float*)d_in[7];
    const float* b_v    = (const float*)d_in[8];
    const float* ln1_g  = (const float*)d_in[9];
    const float* ln1_b  = (const float*)d_in[10];
    const float* ln2_g  = (const float*)d_in[11];
    const float* ln2_b  = (const float*)d_in[12];
    const float* ffn_w1 = (const float*)d_in[13];
    const float* ffn_b1 = (const float*)d_in[14];
    const float* ffn_w2 = (const float*)d_in[15];
    const float* ffn_b2 = (const float*)d_in[16];
    float* out = (float*)d_out;

    void* sp = nullptr;
    cudaGetSymbolAddress(&sp, g_scratch);
    float* s = (float*)sp;
    float* g_q    = s + OFF_Q;
    float* g_out1 = s + OFF_OUT1;
    float* g_h    = s + OFF_H;
    float* g_ffn  = s + OFF_FFN;
    float* g_k    = s + OFF_K;
    float* g_v    = s + OFF_V;

    const dim3 blk(256);
    const dim3 grid_q(DD / 128, NROWS_Q / 128);   // 4 x 64
    const dim3 grid_kv(DD / 128, NROWS_KV / 128); // 4 x 256

    // 1-3: input projections
    sgemm_bias<true ><<<grid_q,  blk>>>(query, w_q, b_q, g_q);
    sgemm_bias<true ><<<grid_kv, blk>>>(key,   w_k, b_k, g_k);
    sgemm_bias<false><<<grid_kv, blk>>>(value, w_v, b_v, g_v);

    // 4: attention downsample + residual + LN1
    attn_ln_kernel<<<NROWS_Q, blk>>>(g_q, g_k, g_v, ln1_g, ln1_b, g_out1);

    // 5-6: FFN
    sgemm_bias<true ><<<grid_q, blk>>>(g_out1, ffn_w1, ffn_b1, g_h);
    sgemm_bias<false><<<grid_q, blk>>>(g_h, ffn_w2, ffn_b2, g_ffn);

    // 7: residual + LN2 -> output
    resid_ln_kernel<<<NROWS_Q, blk>>>(g_out1, g_ffn, ln2_g, ln2_b, out);
}

// round 3
// speedup vs baseline: 1.8613x; 1.8613x over previous
#include <cuda_runtime.h>
#include <cuda_bf16.h>
#include <cstdint>

// ---------------------------------------------------------------------------
// AttentionSampling: B=4, SQ=2048, SK=8192, D=H=512, F=4, fp32.
// GEMMs via mma.sync bf16 (hi/lo split, 3 passes, fp32 accum).
// (tcgen05 unavailable: harness compiles at base sm_100 target.)
// ---------------------------------------------------------------------------

#define DD 512
#define NROWS_Q   8192
#define NROWS_KV  32768
#define EPS 1e-5f

// fp32 scratch: q | out1 | h | ffn | k | v
#define OFF_Q    0
#define OFF_OUT1 (OFF_Q    + (size_t)NROWS_Q  * DD)
#define OFF_H    (OFF_OUT1 + (size_t)NROWS_Q  * DD)
#define OFF_FFN  (OFF_H    + (size_t)NROWS_Q  * DD)
#define OFF_K    (OFF_FFN  + (size_t)NROWS_Q  * DD)
#define OFF_V    (OFF_K    + (size_t)NROWS_KV * DD)
#define SCRATCH_ELEMS (OFF_V + (size_t)NROWS_KV * DD)

__device__ float g_scratch[SCRATCH_ELEMS];
// 5 weights x (hi,lo) x 512x512 bf16, stored [N][K] (transposed)
__device__ __nv_bfloat16 g_wsplit[5u * 2u * 512u * 512u];

// ---------------------------------------------------------------------------
// PTX helpers (base sm_100-legal only: ldmatrix / mma.sync / cp.async)
// ---------------------------------------------------------------------------
__device__ __forceinline__ uint32_t smem_u32(const void* p) {
    uint32_t a;
    asm("{ .reg .u64 t; cvta.to.shared.u64 t, %1; cvt.u32.u64 %0, t; }"
        : "=r"(a) : "l"(p));
    return a;
}
__device__ __forceinline__ void ldsm_x4(uint32_t* r, uint32_t addr) {
    asm volatile("ldmatrix.sync.aligned.m8n8.x4.shared.b16 {%0,%1,%2,%3}, [%4];"
                 : "=r"(r[0]), "=r"(r[1]), "=r"(r[2]), "=r"(r[3]) : "r"(addr));
}
__device__ __forceinline__ void mma16816(float* c, const uint32_t* a, const uint32_t* b) {
    asm volatile(
        "mma.sync.aligned.m16n8k16.row.col.f32.bf16.bf16.f32 "
        "{%0,%1,%2,%3}, {%4,%5,%6,%7}, {%8,%9}, {%0,%1,%2,%3};"
        : "+f"(c[0]), "+f"(c[1]), "+f"(c[2]), "+f"(c[3])
        : "r"(a[0]), "r"(a[1]), "r"(a[2]), "r"(a[3]), "r"(b[0]), "r"(b[1]));
}
__device__ __forceinline__ void cp16(uint32_t saddr, const void* g) {
    asm volatile("cp.async.cg.shared.global [%0], [%1], 16;"
                 :: "r"(saddr), "l"(g) : "memory");
}
__device__ __forceinline__ void cp_commit() {
    asm volatile("cp.async.commit_group;" ::: "memory");
}
__device__ __forceinline__ void cp_wait0() {
    asm volatile("cp.async.wait_group 0;" ::: "memory");
}

// ---------------------------------------------------------------------------
// Weight prep: W[k][n] fp32 -> Th[n][k], Tl[n][k] bf16 (hi/lo split)
// ---------------------------------------------------------------------------
__global__ void prep_weight(const float* __restrict__ W,
                            __nv_bfloat16* __restrict__ Th,
                            __nv_bfloat16* __restrict__ Tl) {
    __shared__ float t[32][33];
    const int bx = blockIdx.x * 32, by = blockIdx.y * 32;
    const int tx = threadIdx.x, ty = threadIdx.y; // 32 x 8
#pragma unroll
    for (int i = 0; i < 32; i += 8)
        t[ty + i][tx] = W[(size_t)(by + ty + i) * DD + bx + tx];
    __syncthreads();
#pragma unroll
    for (int i = 0; i < 32; i += 8) {
        float x = t[tx][ty + i];                  // W[by+tx][bx+ty+i]
        __nv_bfloat16 h = __float2bfloat16(x);
        float lo = x - __bfloat162float(h);
        size_t o = (size_t)(bx + ty + i) * DD + by + tx;
        Th[o] = h;
        Tl[o] = __float2bfloat16(lo);
    }
}

// ---------------------------------------------------------------------------
// HMMA GEMM: C[M,512] = act(A[M,512] @ W[512,512] + bias)
// Wh/Wl bf16 [N=512][K=512] (pre-transposed + split).
// BM=128, BN=128, BK=32, 256 thr (8 warps 2m x 4n; warp tile 64x32).
// Smem per stage: Ah|Al|Bh|Bl, rows of 40 bf16 (80B) -> ldmatrix conflict-free.
// ---------------------------------------------------------------------------
#define BKC 32
#define NCH (DD / BKC)          // 16
#define RSTR 40                 // bf16 elems per smem row
#define RSTRB 80                // bytes per smem row
#define SUBBUF (128 * RSTRB)    // 10240 B
#define SG_AH 0
#define SG_AL (1 * SUBBUF)
#define SG_BH (2 * SUBBUF)
#define SG_BL (3 * SUBBUF)
#define SG_SZ (4 * SUBBUF)      // 40960
#define GEMM_SMEM (2 * SG_SZ)   // 81920

template <bool RELU>
__global__ void __launch_bounds__(256, 1) gemm_mma(
    const float* __restrict__ A, const __nv_bfloat16* __restrict__ Wh,
    const __nv_bfloat16* __restrict__ Wl, const float* __restrict__ bias,
    float* __restrict__ C)
{
    extern __shared__ char sm[];
    const uint32_t sb = smem_u32(sm);

    const int tid = threadIdx.x;
    const int lane = tid & 31, wid = tid >> 5;
    const int wm = (wid & 1) * 64;      // warp m offset
    const int wn = (wid >> 1) * 32;     // warp n offset
    const int bm = blockIdx.y * 128;
    const int bn = blockIdx.x * 128;

    float acc[4][4][4];
#pragma unroll
    for (int i = 0; i < 4; i++)
#pragma unroll
        for (int j = 0; j < 4; j++)
#pragma unroll
            for (int t = 0; t < 4; t++) acc[i][j][t] = 0.f;

    // A gmem->reg mapping: row = tid>>1 (0..127), kbase = (tid&1)*16
    const int arow = tid >> 1;
    const int akb = (tid & 1) * 16;
    const float* Abase = A + (size_t)(bm + arow) * DD + akb;

    float4 ar[4];
    auto ldA = [&](int c) {
        const float* p = Abase + c * BKC;
#pragma unroll
        for (int g = 0; g < 4; g++) ar[g] = *(const float4*)(p + g * 4);
    };
    auto stA = [&](int s) {
        char* st = sm + s * SG_SZ;
#pragma unroll
        for (int g = 0; g < 4; g++) {
            float4 x = ar[g];
            __nv_bfloat16 hx = __float2bfloat16(x.x), hy = __float2bfloat16(x.y);
            __nv_bfloat16 hz = __float2bfloat16(x.z), hw = __float2bfloat16(x.w);
            __nv_bfloat162 h01, h23, l01, l23;
            h01.x = hx; h01.y = hy; h23.x = hz; h23.y = hw;
            l01.x = __float2bfloat16(x.x - __bfloat162float(hx));
            l01.y = __float2bfloat16(x.y - __bfloat162float(hy));
            l23.x = __float2bfloat16(x.z - __bfloat162float(hz));
            l23.y = __float2bfloat16(x.w - __bfloat162float(hw));
            uint2 hv, lv;
            hv.x = *(uint32_t*)&h01; hv.y = *(uint32_t*)&h23;
            lv.x = *(uint32_t*)&l01; lv.y = *(uint32_t*)&l23;
            uint32_t off = (uint32_t)arow * RSTRB + (uint32_t)(akb + g * 4) * 2;
            *(uint2*)(st + SG_AH + off) = hv;
            *(uint2*)(st + SG_AL + off) = lv;
        }
    };
    auto ldB = [&](int c, int s) {
        const uint32_t st = sb + s * SG_SZ;
#pragma unroll
        for (int i = 0; i < 2; i++) {
            int id = i * 256 + tid;          // 0..511
            int n = id >> 2;                 // 0..127
            int ko = (id & 3) * 8;           // bf16 offset within chunk
            size_t g = (size_t)(bn + n) * DD + c * BKC + ko;
            uint32_t off = (uint32_t)n * RSTRB + (uint32_t)ko * 2;
            cp16(st + SG_BH + off, Wh + g);
            cp16(st + SG_BL + off, Wl + g);
        }
        cp_commit();
    };

    // ldmatrix lane addressing (canonical pairings)
    const int a_r = wm + (lane & 15);
    const int a_cb = (lane >> 4) * 16;                 // byte offset of k-half
    const int b_r = wn + ((lane >> 4) << 3) + (lane & 7);
    const int b_cb = ((lane >> 3) & 1) * 16;

    auto compute = [&](int s) {
        const uint32_t st = sb + s * SG_SZ;
#pragma unroll
        for (int ks = 0; ks < 2; ks++) {
            uint32_t ah[4][4], al[4][4], bh[2][4], bl[2][4];
            const uint32_t kbase = (uint32_t)(ks * 32) + 0;
#pragma unroll
            for (int i = 0; i < 4; i++) {
                uint32_t off = (uint32_t)(a_r + i * 16) * RSTRB + kbase + a_cb;
                ldsm_x4(ah[i], st + SG_AH + off);
                ldsm_x4(al[i], st + SG_AL + off);
            }
#pragma unroll
            for (int jp = 0; jp < 2; jp++) {
                uint32_t off = (uint32_t)(b_r + jp * 16) * RSTRB + kbase + b_cb;
                ldsm_x4(bh[jp], st + SG_BH + off);
                ldsm_x4(bl[jp], st + SG_BL + off);
            }
#pragma unroll
            for (int i = 0; i < 4; i++)
#pragma unroll
                for (int j = 0; j < 4; j++) {
                    const uint32_t* bhp = &bh[j >> 1][(j & 1) * 2];
                    const uint32_t* blp = &bl[j >> 1][(j & 1) * 2];
                    mma16816(acc[i][j], ah[i], bhp);
                    mma16816(acc[i][j], ah[i], blp);
                    mma16816(acc[i][j], al[i], bhp);
                }
        }
    };

    // prologue
    ldA(0); stA(0); ldB(0, 0);
    cp_wait0();
    __syncthreads();

#pragma unroll 1
    for (int c = 0; c < NCH; c++) {
        const int s = c & 1;
        if (c + 1 < NCH) { ldB(c + 1, s ^ 1); ldA(c + 1); }
        compute(s);
        if (c + 1 < NCH) {
            stA(s ^ 1);
            cp_wait0();
            __syncthreads();
        }
    }

    // epilogue: bias (+relu) and store
    const int crow = lane >> 2, ccol = (lane & 3) * 2;
#pragma unroll
    for (int i = 0; i < 4; i++) {
        const int r0 = bm + wm + i * 16 + crow;
#pragma unroll
        for (int j = 0; j < 4; j++) {
            const int col = bn + wn + j * 8 + ccol;
            float2 bv = *(const float2*)(bias + col);
            float2 o0, o1;
            o0.x = acc[i][j][0] + bv.x; o0.y = acc[i][j][1] + bv.y;
            o1.x = acc[i][j][2] + bv.x; o1.y = acc[i][j][3] + bv.y;
            if (RELU) {
                o0.x = fmaxf(o0.x, 0.f); o0.y = fmaxf(o0.y, 0.f);
                o1.x = fmaxf(o1.x, 0.f); o1.y = fmaxf(o1.y, 0.f);
            }
            *(float2*)(C + (size_t)r0 * DD + col) = o0;
            *(float2*)(C + (size_t)(r0 + 8) * DD + col) = o1;
        }
    }
}

// ---------------------------------------------------------------------------
// warp reduction
// ---------------------------------------------------------------------------
__device__ __forceinline__ float warp_sum(float x) {
#pragma unroll
    for (int o = 16; o > 0; o >>= 1) x += __shfl_xor_sync(0xffffffffu, x, o);
    return x;
}

// ---------------------------------------------------------------------------
// Fused attention downsampling + residual + LayerNorm1 (one block per row)
// ---------------------------------------------------------------------------
__global__ void __launch_bounds__(256) attn_ln_kernel(
    const float* __restrict__ q, const float* __restrict__ k,
    const float* __restrict__ v, const float* __restrict__ gamma,
    const float* __restrict__ beta, float* __restrict__ out)
{
    const int row = blockIdx.x;
    const float* qr = q + (size_t)row * DD;
    const float* kr = k + (size_t)row * 4 * DD;
    const float* vr = v + (size_t)row * 4 * DD;
    const int tid = threadIdx.x;
    const int lane = tid & 31, wid = tid >> 5;

    float q0 = qr[tid], q1 = qr[tid + 256];

    float p[4];
#pragma unroll
    for (int f = 0; f < 4; f++)
        p[f] = q0 * kr[f * DD + tid] + q1 * kr[f * DD + tid + 256];

    __shared__ float red[4][8];
#pragma unroll
    for (int f = 0; f < 4; f++) {
        float s = warp_sum(p[f]);
        if (lane == 0) red[f][wid] = s;
    }
    __syncthreads();
    __shared__ float wsh[4];
    if (tid < 4) {
        float s = 0.f;
#pragma unroll
        for (int i = 0; i < 8; i++) s += red[tid][i];
        wsh[tid] = s;
    }
    __syncthreads();
    const float w0 = wsh[0], w1 = wsh[1], w2 = wsh[2], w3 = wsh[3];

    float r0 = q0 + w0 * vr[tid]          + w1 * vr[DD + tid]
                  + w2 * vr[2 * DD + tid] + w3 * vr[3 * DD + tid];
    float r1 = q1 + w0 * vr[tid + 256]          + w1 * vr[DD + tid + 256]
                  + w2 * vr[2 * DD + tid + 256] + w3 * vr[3 * DD + tid + 256];

    float s = warp_sum(r0 + r1);
    float ss = warp_sum(r0 * r0 + r1 * r1);
    __shared__ float rs[8], rss[8];
    if (lane == 0) { rs[wid] = s; rss[wid] = ss; }
    __syncthreads();
    __shared__ float mv[2];
    if (tid == 0) {
        float S = 0.f, SS = 0.f;
#pragma unroll
        for (int i = 0; i < 8; i++) { S += rs[i]; SS += rss[i]; }
        float mean = S * (1.f / 512.f);
        float var = SS * (1.f / 512.f) - mean * mean;
        mv[0] = mean; mv[1] = rsqrtf(var + EPS);
    }
    __syncthreads();
    const float mean = mv[0], inv = mv[1];
    float* orow = out + (size_t)row * DD;
    orow[tid]       = (r0 - mean) * inv * gamma[tid]       + beta[tid];
    orow[tid + 256] = (r1 - mean) * inv * gamma[tid + 256] + beta[tid + 256];
}

// ---------------------------------------------------------------------------
// Fused residual + LayerNorm2 -> output
// ---------------------------------------------------------------------------
__global__ void __launch_bounds__(256) resid_ln_kernel(
    const float* __restrict__ a, const float* __restrict__ f,
    const float* __restrict__ gamma, const float* __restrict__ beta,
    float* __restrict__ out)
{
    const int row = blockIdx.x;
    const int tid = threadIdx.x;
    const int lane = tid & 31, wid = tid >> 5;
    const size_t off = (size_t)row * DD;

    float r0 = a[off + tid]       + f[off + tid];
    float r1 = a[off + tid + 256] + f[off + tid + 256];

    float s = warp_sum(r0 + r1);
    float ss = warp_sum(r0 * r0 + r1 * r1);
    __shared__ float rs[8], rss[8];
    if (lane == 0) { rs[wid] = s; rss[wid] = ss; }
    __syncthreads();
    __shared__ float mv[2];
    if (tid == 0) {
        float S = 0.f, SS = 0.f;
#pragma unroll
        for (int i = 0; i < 8; i++) { S += rs[i]; SS += rss[i]; }
        float mean = S * (1.f / 512.f);
        float var = SS * (1.f / 512.f) - mean * mean;
        mv[0] = mean; mv[1] = rsqrtf(var + EPS);
    }
    __syncthreads();
    const float mean = mv[0], inv = mv[1];
    out[off + tid]       = (r0 - mean) * inv * gamma[tid]       + beta[tid];
    out[off + tid + 256] = (r1 - mean) * inv * gamma[tid + 256] + beta[tid + 256];
}

// ---------------------------------------------------------------------------
// Launch
// ---------------------------------------------------------------------------
extern "C" void kernel_launch(void* const* d_in, const int* in_sizes, int n_in,
                              void* d_out, int out_size)
{
    const float* query  = (const float*)d_in[0];
    const float* key    = (const float*)d_in[1];
    const float* value  = (const float*)d_in[2];
    const float* w_q    = (const float*)d_in[3];
    const float* b_q    = (const float*)d_in[4];
    const float* w_k    = (const float*)d_in[5];
    const float* b_k    = (const float*)d_in[6];
    const float* w_v    = (const float*)d_in[7];
    const float* b_v    = (const float*)d_in[8];
    const float* ln1_g  = (const float*)d_in[9];
    const float* ln1_b  = (const float*)d_in[10];
    const float* ln2_g  = (const float*)d_in[11];
    const float* ln2_b  = (const float*)d_in[12];
    const float* ffn_w1 = (const float*)d_in[13];
    const float* ffn_b1 = (const float*)d_in[14];
    const float* ffn_w2 = (const float*)d_in[15];
    const float* ffn_b2 = (const float*)d_in[16];
    float* out = (float*)d_out;

    void* sp = nullptr;
    cudaGetSymbolAddress(&sp, g_scratch);
    float* s = (float*)sp;
    float* g_q    = s + OFF_Q;
    float* g_out1 = s + OFF_OUT1;
    float* g_h    = s + OFF_H;
    float* g_ffn  = s + OFF_FFN;
    float* g_k    = s + OFF_K;
    float* g_v    = s + OFF_V;

    void* wp = nullptr;
    cudaGetSymbolAddress(&wp, g_wsplit);
    __nv_bfloat16* w = (__nv_bfloat16*)wp;
    const size_t WSZ = 512u * 512u;
    __nv_bfloat16* qh = w + 0 * 2 * WSZ; __nv_bfloat16* ql = qh + WSZ;
    __nv_bfloat16* kh = w + 1 * 2 * WSZ; __nv_bfloat16* kl = kh + WSZ;
    __nv_bfloat16* vh = w + 2 * 2 * WSZ; __nv_bfloat16* vl = vh + WSZ;
    __nv_bfloat16* f1h = w + 3 * 2 * WSZ; __nv_bfloat16* f1l = f1h + WSZ;
    __nv_bfloat16* f2h = w + 4 * 2 * WSZ; __nv_bfloat16* f2l = f2h + WSZ;

    cudaFuncSetAttribute(gemm_mma<true>,  cudaFuncAttributeMaxDynamicSharedMemorySize, GEMM_SMEM);
    cudaFuncSetAttribute(gemm_mma<false>, cudaFuncAttributeMaxDynamicSharedMemorySize, GEMM_SMEM);

    // weight prep (tiny)
    dim3 pb(32, 8), pg(16, 16);
    prep_weight<<<pg, pb>>>(w_q,    qh,  ql);
    prep_weight<<<pg, pb>>>(w_k,    kh,  kl);
    prep_weight<<<pg, pb>>>(w_v,    vh,  vl);
    prep_weight<<<pg, pb>>>(ffn_w1, f1h, f1l);
    prep_weight<<<pg, pb>>>(ffn_w2, f2h, f2l);

    const dim3 blk(256);
    const dim3 grid_q(DD / 128, NROWS_Q / 128);   // 4 x 64
    const dim3 grid_kv(DD / 128, NROWS_KV / 128); // 4 x 256

    gemm_mma<true ><<<grid_q,  blk, GEMM_SMEM>>>(query, qh, ql, b_q, g_q);
    gemm_mma<true ><<<grid_kv, blk, GEMM_SMEM>>>(key,   kh, kl, b_k, g_k);
    gemm_mma<false><<<grid_kv, blk, GEMM_SMEM>>>(value, vh, vl, b_v, g_v);

    attn_ln_kernel<<<NROWS_Q, blk>>>(g_q, g_k, g_v, ln1_g, ln1_b, g_out1);

    gemm_mma<true ><<<grid_q, blk, GEMM_SMEM>>>(g_out1, f1h, f1l, ffn_b1, g_h);
    gemm_mma<false><<<grid_q, blk, GEMM_SMEM>>>(g_h,    f2h, f2l, ffn_b2, g_ffn);

    resid_ln_kernel<<<NROWS_Q, blk>>>(g_out1, g_ffn, ln2_g, ln2_b, out);
}